// round 14
// baseline (speedup 1.0000x reference)
#include <cuda_runtime.h>
#include <cuda_fp16.h>
#include <cuda_bf16.h>
#include <cstdint>

// Problem constants (fixed by the dataset)
#define N_NODES   50000
#define F_IN      256
#define F_OUT     64
#define N_EDGES   1600000
#define ALPHA     0.2f

#define SCAN_BLK  256
#define MAX_NB    ((N_NODES + SCAN_BLK - 1) / SCAN_BLK + 8)

// Scratch (static device globals; no allocation allowed)
__device__ __half g_Whh[N_NODES * F_OUT];     // 6.4 MB fp16 features for gathers
__device__ __half g_Wt_hi[F_OUT * F_IN];      // W^T hi, [64][256] fp16
__device__ __half g_Wt_lo[F_OUT * F_IN];      // W^T lo
__device__ float  g_ssrc[N_NODES];
__device__ float  g_sdst[N_NODES];
__device__ int    g_count[N_NODES];
__device__ int    g_rowstart[N_NODES];
__device__ int    g_blocksum[MAX_NB];
__device__ int    g_rank[N_EDGES];            // per-edge rank within its src row
__device__ int    g_edst[N_EDGES];            // src-sorted dst only, 6.4 MB

// ---------------------------------------------------------------------------
// Kernel 0: W prep — split fp32 W into fp16 hi/lo, transposed to [N][K].
// ---------------------------------------------------------------------------
__global__ void wprep_kernel(const float* __restrict__ W,
                             __half* __restrict__ wh, __half* __restrict__ wl)
{
    int i = blockIdx.x * blockDim.x + threadIdx.x;
    if (i >= F_IN * F_OUT) return;
    int n = i & (F_OUT - 1);
    int k = i >> 6;
    float v = W[(size_t)k * F_OUT + n];
    __half h = __float2half_rn(v);
    __half l = __float2half_rn(v - __half2float(h));
    wh[(size_t)n * F_IN + k] = h;
    wl[(size_t)n * F_IN + k] = l;
}

// ---------------------------------------------------------------------------
// Kernel 1: Wh = x @ W via split-fp16 tensor-core MMA (m16n8k16, fp32 accum).
// ---------------------------------------------------------------------------
#define BM   128
#define BKP  40

#define MMA16816(c, a0, a1, a2, a3, b0, b1)                                   \
    asm volatile("mma.sync.aligned.m16n8k16.row.col.f32.f16.f16.f32 "        \
                 "{%0,%1,%2,%3}, {%4,%5,%6,%7}, {%8,%9}, {%0,%1,%2,%3};"     \
                 : "+f"(c[0]), "+f"(c[1]), "+f"(c[2]), "+f"(c[3])            \
                 : "r"(a0), "r"(a1), "r"(a2), "r"(a3), "r"(b0), "r"(b1))

__global__ __launch_bounds__(256) void gemm_kernel(
    const float* __restrict__ x,
    const __half* __restrict__ Wth, const __half* __restrict__ Wtl,
    const float* __restrict__ a,
    __half* __restrict__ Whh,
    float* __restrict__ ssrc, float* __restrict__ sdst, int nrows)
{
    __shared__ __half Ah[BM][BKP];
    __shared__ __half Al[BM][BKP];
    __shared__ __half Bh[F_OUT][BKP];
    __shared__ __half Bl[F_OUT][BKP];
    __shared__ float  sp[BM];
    __shared__ float  sq[BM];
    __shared__ float  sa[2 * F_OUT];

    const int tid  = threadIdx.x;
    const int block_row = blockIdx.x * BM;
    const int warp = tid >> 5, lane = tid & 31;
    const int g    = lane >> 2, tig = lane & 3;
    const int wm   = warp >> 1, wn = warp & 1;
    const int m0   = wm * 32;
    const int n0   = wn * 32;

    if (tid < 2 * F_OUT) sa[tid] = a[tid];
    if (tid < BM) { sp[tid] = 0.f; sq[tid] = 0.f; }

    float c[2][4][4] = {};

    for (int k0 = 0; k0 < F_IN; k0 += 32) {
        #pragma unroll
        for (int i = 0; i < 4; i++) {
            int idx = tid + i * 256;
            int m   = idx >> 3;
            int kq  = (idx & 7) * 4;
            int gm  = block_row + m;
            float4 v = make_float4(0.f, 0.f, 0.f, 0.f);
            if (gm < nrows)
                v = *reinterpret_cast<const float4*>(x + (size_t)gm * F_IN + k0 + kq);
            __half hx = __float2half_rn(v.x);
            __half hy = __float2half_rn(v.y);
            __half hz = __float2half_rn(v.z);
            __half hw = __float2half_rn(v.w);
            __half lx = __float2half_rn(v.x - __half2float(hx));
            __half ly = __float2half_rn(v.y - __half2float(hy));
            __half lz = __float2half_rn(v.z - __half2float(hz));
            __half lw = __float2half_rn(v.w - __half2float(hw));
            __half2* ph = reinterpret_cast<__half2*>(&Ah[m][kq]);
            ph[0] = __halves2half2(hx, hy);
            ph[1] = __halves2half2(hz, hw);
            __half2* pl = reinterpret_cast<__half2*>(&Al[m][kq]);
            pl[0] = __halves2half2(lx, ly);
            pl[1] = __halves2half2(lz, lw);
        }
        {
            int n  = tid >> 2;
            int kq = (tid & 3) * 8;
            *reinterpret_cast<uint4*>(&Bh[n][kq]) =
                *reinterpret_cast<const uint4*>(Wth + (size_t)n * F_IN + k0 + kq);
            *reinterpret_cast<uint4*>(&Bl[n][kq]) =
                *reinterpret_cast<const uint4*>(Wtl + (size_t)n * F_IN + k0 + kq);
        }
        __syncthreads();

        #pragma unroll
        for (int ks = 0; ks < 32; ks += 16) {
            const int kk = ks + tig * 2;
            unsigned int ah[2][4], al[2][4];
            #pragma unroll
            for (int mt = 0; mt < 2; mt++) {
                int r0 = m0 + mt * 16 + g;
                ah[mt][0] = *reinterpret_cast<unsigned int*>(&Ah[r0    ][kk    ]);
                ah[mt][1] = *reinterpret_cast<unsigned int*>(&Ah[r0 + 8][kk    ]);
                ah[mt][2] = *reinterpret_cast<unsigned int*>(&Ah[r0    ][kk + 8]);
                ah[mt][3] = *reinterpret_cast<unsigned int*>(&Ah[r0 + 8][kk + 8]);
                al[mt][0] = *reinterpret_cast<unsigned int*>(&Al[r0    ][kk    ]);
                al[mt][1] = *reinterpret_cast<unsigned int*>(&Al[r0 + 8][kk    ]);
                al[mt][2] = *reinterpret_cast<unsigned int*>(&Al[r0    ][kk + 8]);
                al[mt][3] = *reinterpret_cast<unsigned int*>(&Al[r0 + 8][kk + 8]);
            }
            #pragma unroll
            for (int nt = 0; nt < 4; nt++) {
                int nr = n0 + nt * 8 + g;
                unsigned int bh0 = *reinterpret_cast<unsigned int*>(&Bh[nr][kk    ]);
                unsigned int bh1 = *reinterpret_cast<unsigned int*>(&Bh[nr][kk + 8]);
                unsigned int bl0 = *reinterpret_cast<unsigned int*>(&Bl[nr][kk    ]);
                unsigned int bl1 = *reinterpret_cast<unsigned int*>(&Bl[nr][kk + 8]);
                #pragma unroll
                for (int mt = 0; mt < 2; mt++) {
                    MMA16816(c[mt][nt], ah[mt][0], ah[mt][1], ah[mt][2], ah[mt][3], bh0, bh1);
                    MMA16816(c[mt][nt], ah[mt][0], ah[mt][1], ah[mt][2], ah[mt][3], bl0, bl1);
                    MMA16816(c[mt][nt], al[mt][0], al[mt][1], al[mt][2], al[mt][3], bh0, bh1);
                }
            }
        }
        __syncthreads();
    }

    #pragma unroll
    for (int mt = 0; mt < 2; mt++) {
        float p0 = 0.f, q0 = 0.f, p1 = 0.f, q1 = 0.f;
        #pragma unroll
        for (int nt = 0; nt < 4; nt++) {
            int col = n0 + nt * 8 + tig * 2;
            float a1x = sa[col],      a1y = sa[col + 1];
            float a2x = sa[64 + col], a2y = sa[64 + col + 1];
            p0 += c[mt][nt][0] * a1x + c[mt][nt][1] * a1y;
            q0 += c[mt][nt][0] * a2x + c[mt][nt][1] * a2y;
            p1 += c[mt][nt][2] * a1x + c[mt][nt][3] * a1y;
            q1 += c[mt][nt][2] * a2x + c[mt][nt][3] * a2y;

            int r = block_row + m0 + mt * 16 + g;
            if (r < nrows) {
                *reinterpret_cast<__half2*>(Whh + (size_t)r * F_OUT + col) =
                    __floats2half2_rn(c[mt][nt][0], c[mt][nt][1]);
            }
            if (r + 8 < nrows) {
                *reinterpret_cast<__half2*>(Whh + (size_t)(r + 8) * F_OUT + col) =
                    __floats2half2_rn(c[mt][nt][2], c[mt][nt][3]);
            }
        }
        #pragma unroll
        for (int o = 1; o < 4; o <<= 1) {
            p0 += __shfl_xor_sync(0xffffffffu, p0, o);
            q0 += __shfl_xor_sync(0xffffffffu, q0, o);
            p1 += __shfl_xor_sync(0xffffffffu, p1, o);
            q1 += __shfl_xor_sync(0xffffffffu, q1, o);
        }
        if (tig == 0) {
            int rl = m0 + mt * 16 + g;
            atomicAdd(&sp[rl], p0);
            atomicAdd(&sq[rl], q0);
            atomicAdd(&sp[rl + 8], p1);
            atomicAdd(&sq[rl + 8], q1);
        }
    }
    __syncthreads();

    if (tid < BM) {
        int m = block_row + tid;
        if (m < nrows) {
            ssrc[m] = sp[tid];
            sdst[m] = sq[tid];
        }
    }
}

// ---------------------------------------------------------------------------
// Kernel 3: histogram of src + per-edge rank capture — 8 edges per thread
// (two int4 loads -> 8 independent value-returning atomics in flight).
// ---------------------------------------------------------------------------
__global__ __launch_bounds__(256) void hist_kernel(
    const int* __restrict__ src, int* __restrict__ count,
    int* __restrict__ rank, int nedges)
{
    int i = blockIdx.x * blockDim.x + threadIdx.x;   // oct index
    int e = i * 8;
    if (e + 7 < nedges) {
        int4 s0 = *reinterpret_cast<const int4*>(src + e);
        int4 s1 = *reinterpret_cast<const int4*>(src + e + 4);
        int4 r0, r1;
        r0.x = atomicAdd(count + s0.x, 1);
        r0.y = atomicAdd(count + s0.y, 1);
        r0.z = atomicAdd(count + s0.z, 1);
        r0.w = atomicAdd(count + s0.w, 1);
        r1.x = atomicAdd(count + s1.x, 1);
        r1.y = atomicAdd(count + s1.y, 1);
        r1.z = atomicAdd(count + s1.z, 1);
        r1.w = atomicAdd(count + s1.w, 1);
        *reinterpret_cast<int4*>(rank + e)     = r0;
        *reinterpret_cast<int4*>(rank + e + 4) = r1;
    } else {
        for (int k = e; k < nedges; k++)
            rank[k] = atomicAdd(count + __ldg(src + k), 1);
    }
}

// ---------------------------------------------------------------------------
// Kernels 4a/4b/4c: two-level parallel exclusive scan over counts.
// ---------------------------------------------------------------------------
__global__ __launch_bounds__(SCAN_BLK) void block_sum_kernel(
    const int* __restrict__ count, int* __restrict__ blocksum, int n)
{
    __shared__ int sdata[SCAN_BLK];
    int i = blockIdx.x * SCAN_BLK + threadIdx.x;
    int v = (i < n) ? count[i] : 0;
    sdata[threadIdx.x] = v;
    __syncthreads();
    #pragma unroll
    for (int off = SCAN_BLK / 2; off > 0; off >>= 1) {
        if (threadIdx.x < off) sdata[threadIdx.x] += sdata[threadIdx.x + off];
        __syncthreads();
    }
    if (threadIdx.x == 0) blocksum[blockIdx.x] = sdata[0];
}

__global__ __launch_bounds__(SCAN_BLK) void scan_tops_kernel(
    int* __restrict__ blocksum, int nb)
{
    __shared__ int sdata[SCAN_BLK];
    int tid = threadIdx.x;
    sdata[tid] = (tid < nb) ? blocksum[tid] : 0;
    __syncthreads();
    #pragma unroll
    for (int off = 1; off < SCAN_BLK; off <<= 1) {
        int v = (tid >= off) ? sdata[tid - off] : 0;
        __syncthreads();
        sdata[tid] += v;
        __syncthreads();
    }
    if (tid < nb) blocksum[tid] = (tid > 0) ? sdata[tid - 1] : 0;
}

__global__ __launch_bounds__(SCAN_BLK) void scan_final_kernel(
    const int* __restrict__ count, const int* __restrict__ blocksum,
    int* __restrict__ rowstart, int n)
{
    __shared__ int sdata[SCAN_BLK];
    int tid = threadIdx.x;
    int i = blockIdx.x * SCAN_BLK + tid;
    int v = (i < n) ? count[i] : 0;
    sdata[tid] = v;
    __syncthreads();
    #pragma unroll
    for (int off = 1; off < SCAN_BLK; off <<= 1) {
        int t = (tid >= off) ? sdata[tid - off] : 0;
        __syncthreads();
        sdata[tid] += t;
        __syncthreads();
    }
    if (i < n) {
        rowstart[i] = blocksum[blockIdx.x] + sdata[tid] - v;   // exclusive
    }
}

// ---------------------------------------------------------------------------
// Kernel 5: scatter — pos = rowstart[src] + rank[e]; NO atomics.
// ---------------------------------------------------------------------------
__global__ __launch_bounds__(256) void scatter_kernel(
    const int* __restrict__ src, const int* __restrict__ dst,
    const int* __restrict__ rowstart, const int* __restrict__ rank,
    int* __restrict__ edst, int nedges)
{
    int i = blockIdx.x * blockDim.x + threadIdx.x;   // quad index
    int e = i * 4;
    if (e + 3 < nedges) {
        int4 s = *reinterpret_cast<const int4*>(src + e);
        int4 d = *reinterpret_cast<const int4*>(dst + e);
        int4 r = *reinterpret_cast<const int4*>(rank + e);
        edst[__ldg(rowstart + s.x) + r.x] = d.x;
        edst[__ldg(rowstart + s.y) + r.y] = d.y;
        edst[__ldg(rowstart + s.z) + r.z] = d.z;
        edst[__ldg(rowstart + s.w) + r.w] = d.w;
    } else {
        for (int k = e; k < nedges; k++) {
            int s = __ldg(src + k);
            edst[__ldg(rowstart + s) + __ldg(rank + k)] = __ldg(dst + k);
        }
    }
}

// ---------------------------------------------------------------------------
// Kernel 6: aggregation (exact R10 structure — measured best, do not touch).
// ---------------------------------------------------------------------------
__global__ __launch_bounds__(256) void aggregate_kernel(
    const int* __restrict__ edst, const int* __restrict__ rowstart,
    const int* __restrict__ count,
    const float* __restrict__ ssrc, const float* __restrict__ sdst,
    const __half* __restrict__ Whh,
    float* __restrict__ out, int nrows)
{
    const int node = blockIdx.x * 32 + (threadIdx.x >> 3);
    const int t    = threadIdx.x & 7;
    const int lane = threadIdx.x & 31;
    const int base = lane & 24;
    const unsigned grpmask = 0xffu << base;
    if (node >= nrows) return;

    const int   start = __ldg(rowstart + node);
    const int   cnt   = __ldg(count + node);
    const float s0    = __ldg(ssrc + node);

    float a0 = 0.f, a1 = 0.f, a2 = 0.f, a3 = 0.f;
    float a4 = 0.f, a5 = 0.f, a6 = 0.f, a7 = 0.f;
    float wsum = 0.f;

    for (int j = 0; j < cnt; j += 8) {
        unsigned pk = 0;
        if (j + t < cnt) {
            int d = __ldg(edst + start + j + t);
            float score = s0 + __ldg(sdst + d);
            float l = score > 0.f ? score : ALPHA * score;
            float w = __expf(-l);
            pk = ((unsigned)d << 16) |
                 (unsigned)__half_as_ushort(__float2half_rn(w));
        }

        #pragma unroll
        for (int k = 0; k < 8; k++) {
            unsigned p  = __shfl_sync(grpmask, pk, base + k);
            int      dd = (int)(p >> 16);
            float    ww = __half2float(__ushort_as_half((unsigned short)(p & 0xffffu)));
            uint4 hv = __ldg(reinterpret_cast<const uint4*>(Whh + (size_t)dd * F_OUT) + t);
            float2 f0 = __half22float2(*reinterpret_cast<__half2*>(&hv.x));
            float2 f1 = __half22float2(*reinterpret_cast<__half2*>(&hv.y));
            float2 f2 = __half22float2(*reinterpret_cast<__half2*>(&hv.z));
            float2 f3 = __half22float2(*reinterpret_cast<__half2*>(&hv.w));
            a0 += ww * f0.x; a1 += ww * f0.y;
            a2 += ww * f1.x; a3 += ww * f1.y;
            a4 += ww * f2.x; a5 += ww * f2.y;
            a6 += ww * f3.x; a7 += ww * f3.y;
            wsum += ww;
        }
    }

    const float inv = 1.0f / wsum;
    a0 *= inv; a1 *= inv; a2 *= inv; a3 *= inv;
    a4 *= inv; a5 *= inv; a6 *= inv; a7 *= inv;
    a0 = a0 > 0.f ? a0 : expm1f(a0);
    a1 = a1 > 0.f ? a1 : expm1f(a1);
    a2 = a2 > 0.f ? a2 : expm1f(a2);
    a3 = a3 > 0.f ? a3 : expm1f(a3);
    a4 = a4 > 0.f ? a4 : expm1f(a4);
    a5 = a5 > 0.f ? a5 : expm1f(a5);
    a6 = a6 > 0.f ? a6 : expm1f(a6);
    a7 = a7 > 0.f ? a7 : expm1f(a7);

    float4* op = reinterpret_cast<float4*>(out + (size_t)node * F_OUT + t * 8);
    op[0] = make_float4(a0, a1, a2, a3);
    op[1] = make_float4(a4, a5, a6, a7);
}

// ---------------------------------------------------------------------------
// Launch — two independent chains captured as parallel graph branches.
// ---------------------------------------------------------------------------
extern "C" void kernel_launch(void* const* d_in, const int* in_sizes, int n_in,
                              void* d_out, int out_size)
{
    const float* x    = (const float*)d_in[0];
    const int*   edge = (const int*)d_in[1];
    const float* W    = (const float*)d_in[2];
    const float* a    = (const float*)d_in[3];
    float*       out  = (float*)d_out;

    const int nrows  = in_sizes[0] / F_IN;     // 50000
    const int nedges = in_sizes[1] / 2;        // 1600000
    const int* src = edge;
    const int* dst = edge + nedges;

    float *ssrc, *sdst;
    __half *Whh, *Wth, *Wtl;
    int *count, *rowstart, *blocksum, *rank, *edst;
    cudaGetSymbolAddress((void**)&Whh,      g_Whh);
    cudaGetSymbolAddress((void**)&Wth,      g_Wt_hi);
    cudaGetSymbolAddress((void**)&Wtl,      g_Wt_lo);
    cudaGetSymbolAddress((void**)&ssrc,     g_ssrc);
    cudaGetSymbolAddress((void**)&sdst,     g_sdst);
    cudaGetSymbolAddress((void**)&count,    g_count);
    cudaGetSymbolAddress((void**)&rowstart, g_rowstart);
    cudaGetSymbolAddress((void**)&blocksum, g_blocksum);
    cudaGetSymbolAddress((void**)&rank,     g_rank);
    cudaGetSymbolAddress((void**)&edst,     g_edst);

    const int nb = (nrows + SCAN_BLK - 1) / SCAN_BLK;
    const int qthreads = (nedges + 3) / 4;
    const int othreads = (nedges + 7) / 8;

    static cudaStream_t s2 = nullptr;
    static cudaEvent_t  ev_fork = nullptr, ev_join = nullptr;
    if (s2 == nullptr) {
        cudaStreamCreateWithFlags(&s2, cudaStreamNonBlocking);
        cudaEventCreateWithFlags(&ev_fork, cudaEventDisableTiming);
        cudaEventCreateWithFlags(&ev_join, cudaEventDisableTiming);
    }

    // ---- fork
    cudaEventRecord(ev_fork, 0);
    cudaStreamWaitEvent(s2, ev_fork, 0);

    // ---- chain 1 (main stream): features + scores
    wprep_kernel<<<(F_IN * F_OUT + 255) / 256, 256>>>(W, Wth, Wtl);
    gemm_kernel<<<(nrows + BM - 1) / BM, 256>>>(x, Wth, Wtl, a, Whh, ssrc, sdst, nrows);

    // ---- chain 2 (s2): edge sorting (rank-based, single atomic pass)
    cudaMemsetAsync(count, 0, (size_t)nrows * sizeof(int), s2);
    hist_kernel<<<(othreads + 255) / 256, 256, 0, s2>>>(src, count, rank, nedges);
    block_sum_kernel<<<nb, SCAN_BLK, 0, s2>>>(count, blocksum, nrows);
    scan_tops_kernel<<<1, SCAN_BLK, 0, s2>>>(blocksum, nb);
    scan_final_kernel<<<nb, SCAN_BLK, 0, s2>>>(count, blocksum, rowstart, nrows);
    scatter_kernel<<<(qthreads + 255) / 256, 256, 0, s2>>>(src, dst, rowstart,
                                                           rank, edst, nedges);

    // ---- join
    cudaEventRecord(ev_join, s2);
    cudaStreamWaitEvent(0, ev_join, 0);

    // ---- aggregate + finalize
    aggregate_kernel<<<(nrows + 31) / 32, 256>>>(edst, rowstart, count,
                                                 ssrc, sdst, Whh, out, nrows);
}

// round 15
// speedup vs baseline: 1.0393x; 1.0393x over previous
#include <cuda_runtime.h>
#include <cuda_fp16.h>
#include <cuda_bf16.h>
#include <cstdint>

// Problem constants (fixed by the dataset)
#define N_NODES   50000
#define F_IN      256
#define F_OUT     64
#define N_EDGES   1600000
#define ALPHA     0.2f

#define SCAN_BLK  256
#define MAX_NB    ((N_NODES + SCAN_BLK - 1) / SCAN_BLK + 8)

// Scratch (static device globals; no allocation allowed)
__device__ __half g_Whh[N_NODES * F_OUT];     // 6.4 MB fp16 features for gathers
__device__ __half g_Wt_hi[F_OUT * F_IN];      // W^T hi, [64][256] fp16
__device__ __half g_Wt_lo[F_OUT * F_IN];      // W^T lo
__device__ float  g_ssrc[N_NODES];
__device__ float  g_sdst[N_NODES];
__device__ int    g_count[N_NODES];
__device__ int    g_rowstart[N_NODES];
__device__ int    g_blocksum[MAX_NB];
__device__ int    g_rank[N_EDGES];            // per-edge rank within its src row
__device__ int    g_edst[N_EDGES];            // src-sorted dst only, 6.4 MB

// ---------------------------------------------------------------------------
// Kernel 0: W prep — split fp32 W into fp16 hi/lo, transposed to [N][K].
// ---------------------------------------------------------------------------
__global__ void wprep_kernel(const float* __restrict__ W,
                             __half* __restrict__ wh, __half* __restrict__ wl)
{
    int i = blockIdx.x * blockDim.x + threadIdx.x;
    if (i >= F_IN * F_OUT) return;
    int n = i & (F_OUT - 1);
    int k = i >> 6;
    float v = W[(size_t)k * F_OUT + n];
    __half h = __float2half_rn(v);
    __half l = __float2half_rn(v - __half2float(h));
    wh[(size_t)n * F_IN + k] = h;
    wl[(size_t)n * F_IN + k] = l;
}

// ---------------------------------------------------------------------------
// Kernel 1: Wh = x @ W via split-fp16 tensor-core MMA (m16n8k16, fp32 accum).
// ---------------------------------------------------------------------------
#define BM   128
#define BKP  40

#define MMA16816(c, a0, a1, a2, a3, b0, b1)                                   \
    asm volatile("mma.sync.aligned.m16n8k16.row.col.f32.f16.f16.f32 "        \
                 "{%0,%1,%2,%3}, {%4,%5,%6,%7}, {%8,%9}, {%0,%1,%2,%3};"     \
                 : "+f"(c[0]), "+f"(c[1]), "+f"(c[2]), "+f"(c[3])            \
                 : "r"(a0), "r"(a1), "r"(a2), "r"(a3), "r"(b0), "r"(b1))

__global__ __launch_bounds__(256) void gemm_kernel(
    const float* __restrict__ x,
    const __half* __restrict__ Wth, const __half* __restrict__ Wtl,
    const float* __restrict__ a,
    __half* __restrict__ Whh,
    float* __restrict__ ssrc, float* __restrict__ sdst, int nrows)
{
    __shared__ __half Ah[BM][BKP];
    __shared__ __half Al[BM][BKP];
    __shared__ __half Bh[F_OUT][BKP];
    __shared__ __half Bl[F_OUT][BKP];
    __shared__ float  sp[BM];
    __shared__ float  sq[BM];
    __shared__ float  sa[2 * F_OUT];

    const int tid  = threadIdx.x;
    const int block_row = blockIdx.x * BM;
    const int warp = tid >> 5, lane = tid & 31;
    const int g    = lane >> 2, tig = lane & 3;
    const int wm   = warp >> 1, wn = warp & 1;
    const int m0   = wm * 32;
    const int n0   = wn * 32;

    if (tid < 2 * F_OUT) sa[tid] = a[tid];
    if (tid < BM) { sp[tid] = 0.f; sq[tid] = 0.f; }

    float c[2][4][4] = {};

    for (int k0 = 0; k0 < F_IN; k0 += 32) {
        #pragma unroll
        for (int i = 0; i < 4; i++) {
            int idx = tid + i * 256;
            int m   = idx >> 3;
            int kq  = (idx & 7) * 4;
            int gm  = block_row + m;
            float4 v = make_float4(0.f, 0.f, 0.f, 0.f);
            if (gm < nrows)
                v = *reinterpret_cast<const float4*>(x + (size_t)gm * F_IN + k0 + kq);
            __half hx = __float2half_rn(v.x);
            __half hy = __float2half_rn(v.y);
            __half hz = __float2half_rn(v.z);
            __half hw = __float2half_rn(v.w);
            __half lx = __float2half_rn(v.x - __half2float(hx));
            __half ly = __float2half_rn(v.y - __half2float(hy));
            __half lz = __float2half_rn(v.z - __half2float(hz));
            __half lw = __float2half_rn(v.w - __half2float(hw));
            __half2* ph = reinterpret_cast<__half2*>(&Ah[m][kq]);
            ph[0] = __halves2half2(hx, hy);
            ph[1] = __halves2half2(hz, hw);
            __half2* pl = reinterpret_cast<__half2*>(&Al[m][kq]);
            pl[0] = __halves2half2(lx, ly);
            pl[1] = __halves2half2(lz, lw);
        }
        {
            int n  = tid >> 2;
            int kq = (tid & 3) * 8;
            *reinterpret_cast<uint4*>(&Bh[n][kq]) =
                *reinterpret_cast<const uint4*>(Wth + (size_t)n * F_IN + k0 + kq);
            *reinterpret_cast<uint4*>(&Bl[n][kq]) =
                *reinterpret_cast<const uint4*>(Wtl + (size_t)n * F_IN + k0 + kq);
        }
        __syncthreads();

        #pragma unroll
        for (int ks = 0; ks < 32; ks += 16) {
            const int kk = ks + tig * 2;
            unsigned int ah[2][4], al[2][4];
            #pragma unroll
            for (int mt = 0; mt < 2; mt++) {
                int r0 = m0 + mt * 16 + g;
                ah[mt][0] = *reinterpret_cast<unsigned int*>(&Ah[r0    ][kk    ]);
                ah[mt][1] = *reinterpret_cast<unsigned int*>(&Ah[r0 + 8][kk    ]);
                ah[mt][2] = *reinterpret_cast<unsigned int*>(&Ah[r0    ][kk + 8]);
                ah[mt][3] = *reinterpret_cast<unsigned int*>(&Ah[r0 + 8][kk + 8]);
                al[mt][0] = *reinterpret_cast<unsigned int*>(&Al[r0    ][kk    ]);
                al[mt][1] = *reinterpret_cast<unsigned int*>(&Al[r0 + 8][kk    ]);
                al[mt][2] = *reinterpret_cast<unsigned int*>(&Al[r0    ][kk + 8]);
                al[mt][3] = *reinterpret_cast<unsigned int*>(&Al[r0 + 8][kk + 8]);
            }
            #pragma unroll
            for (int nt = 0; nt < 4; nt++) {
                int nr = n0 + nt * 8 + g;
                unsigned int bh0 = *reinterpret_cast<unsigned int*>(&Bh[nr][kk    ]);
                unsigned int bh1 = *reinterpret_cast<unsigned int*>(&Bh[nr][kk + 8]);
                unsigned int bl0 = *reinterpret_cast<unsigned int*>(&Bl[nr][kk    ]);
                unsigned int bl1 = *reinterpret_cast<unsigned int*>(&Bl[nr][kk + 8]);
                #pragma unroll
                for (int mt = 0; mt < 2; mt++) {
                    MMA16816(c[mt][nt], ah[mt][0], ah[mt][1], ah[mt][2], ah[mt][3], bh0, bh1);
                    MMA16816(c[mt][nt], ah[mt][0], ah[mt][1], ah[mt][2], ah[mt][3], bl0, bl1);
                    MMA16816(c[mt][nt], al[mt][0], al[mt][1], al[mt][2], al[mt][3], bh0, bh1);
                }
            }
        }
        __syncthreads();
    }

    #pragma unroll
    for (int mt = 0; mt < 2; mt++) {
        float p0 = 0.f, q0 = 0.f, p1 = 0.f, q1 = 0.f;
        #pragma unroll
        for (int nt = 0; nt < 4; nt++) {
            int col = n0 + nt * 8 + tig * 2;
            float a1x = sa[col],      a1y = sa[col + 1];
            float a2x = sa[64 + col], a2y = sa[64 + col + 1];
            p0 += c[mt][nt][0] * a1x + c[mt][nt][1] * a1y;
            q0 += c[mt][nt][0] * a2x + c[mt][nt][1] * a2y;
            p1 += c[mt][nt][2] * a1x + c[mt][nt][3] * a1y;
            q1 += c[mt][nt][2] * a2x + c[mt][nt][3] * a2y;

            int r = block_row + m0 + mt * 16 + g;
            if (r < nrows) {
                *reinterpret_cast<__half2*>(Whh + (size_t)r * F_OUT + col) =
                    __floats2half2_rn(c[mt][nt][0], c[mt][nt][1]);
            }
            if (r + 8 < nrows) {
                *reinterpret_cast<__half2*>(Whh + (size_t)(r + 8) * F_OUT + col) =
                    __floats2half2_rn(c[mt][nt][2], c[mt][nt][3]);
            }
        }
        #pragma unroll
        for (int o = 1; o < 4; o <<= 1) {
            p0 += __shfl_xor_sync(0xffffffffu, p0, o);
            q0 += __shfl_xor_sync(0xffffffffu, q0, o);
            p1 += __shfl_xor_sync(0xffffffffu, p1, o);
            q1 += __shfl_xor_sync(0xffffffffu, q1, o);
        }
        if (tig == 0) {
            int rl = m0 + mt * 16 + g;
            atomicAdd(&sp[rl], p0);
            atomicAdd(&sq[rl], q0);
            atomicAdd(&sp[rl + 8], p1);
            atomicAdd(&sq[rl + 8], q1);
        }
    }
    __syncthreads();

    if (tid < BM) {
        int m = block_row + tid;
        if (m < nrows) {
            ssrc[m] = sp[tid];
            sdst[m] = sq[tid];
        }
    }
}

// ---------------------------------------------------------------------------
// Kernel 3: histogram of src + per-edge rank capture (4 edges per thread).
// (R13 configuration — measured best.)
// ---------------------------------------------------------------------------
__global__ __launch_bounds__(256) void hist_kernel(
    const int* __restrict__ src, int* __restrict__ count,
    int* __restrict__ rank, int nedges)
{
    int i = blockIdx.x * blockDim.x + threadIdx.x;   // quad index
    int e = i * 4;
    if (e + 3 < nedges) {
        int4 s = *reinterpret_cast<const int4*>(src + e);
        int4 r;
        r.x = atomicAdd(count + s.x, 1);
        r.y = atomicAdd(count + s.y, 1);
        r.z = atomicAdd(count + s.z, 1);
        r.w = atomicAdd(count + s.w, 1);
        *reinterpret_cast<int4*>(rank + e) = r;
    } else {
        for (int k = e; k < nedges; k++)
            rank[k] = atomicAdd(count + __ldg(src + k), 1);
    }
}

// ---------------------------------------------------------------------------
// Kernel 4a: per-block sums of counts.
// ---------------------------------------------------------------------------
__global__ __launch_bounds__(SCAN_BLK) void block_sum_kernel(
    const int* __restrict__ count, int* __restrict__ blocksum, int n)
{
    __shared__ int sdata[SCAN_BLK];
    int i = blockIdx.x * SCAN_BLK + threadIdx.x;
    int v = (i < n) ? count[i] : 0;
    sdata[threadIdx.x] = v;
    __syncthreads();
    #pragma unroll
    for (int off = SCAN_BLK / 2; off > 0; off >>= 1) {
        if (threadIdx.x < off) sdata[threadIdx.x] += sdata[threadIdx.x + off];
        __syncthreads();
    }
    if (threadIdx.x == 0) blocksum[blockIdx.x] = sdata[0];
}

// ---------------------------------------------------------------------------
// Kernel 4b: final scan. Each block computes its own offset by reducing
// blocksum[b < blockIdx] (nb <= 256, one load per thread), then does the
// intra-block exclusive scan. Eliminates the separate scan_tops kernel.
// ---------------------------------------------------------------------------
__global__ __launch_bounds__(SCAN_BLK) void scan_final_kernel(
    const int* __restrict__ count, const int* __restrict__ blocksum,
    int* __restrict__ rowstart, int n, int nb)
{
    __shared__ int sdata[SCAN_BLK];
    __shared__ int soff[SCAN_BLK];
    const int tid = threadIdx.x;
    const int bid = blockIdx.x;

    // block offset = sum of blocksum[0 .. bid-1]
    soff[tid] = (tid < bid && tid < nb) ? blocksum[tid] : 0;
    __syncthreads();
    #pragma unroll
    for (int off = SCAN_BLK / 2; off > 0; off >>= 1) {
        if (tid < off) soff[tid] += soff[tid + off];
        __syncthreads();
    }
    const int block_off = soff[0];
    __syncthreads();

    // intra-block inclusive scan of counts
    int i = bid * SCAN_BLK + tid;
    int v = (i < n) ? count[i] : 0;
    sdata[tid] = v;
    __syncthreads();
    #pragma unroll
    for (int off = 1; off < SCAN_BLK; off <<= 1) {
        int t = (tid >= off) ? sdata[tid - off] : 0;
        __syncthreads();
        sdata[tid] += t;
        __syncthreads();
    }
    if (i < n) {
        rowstart[i] = block_off + sdata[tid] - v;   // exclusive
    }
}

// ---------------------------------------------------------------------------
// Kernel 5: scatter — pos = rowstart[src] + rank[e]; NO atomics.
// ---------------------------------------------------------------------------
__global__ __launch_bounds__(256) void scatter_kernel(
    const int* __restrict__ src, const int* __restrict__ dst,
    const int* __restrict__ rowstart, const int* __restrict__ rank,
    int* __restrict__ edst, int nedges)
{
    int i = blockIdx.x * blockDim.x + threadIdx.x;   // quad index
    int e = i * 4;
    if (e + 3 < nedges) {
        int4 s = *reinterpret_cast<const int4*>(src + e);
        int4 d = *reinterpret_cast<const int4*>(dst + e);
        int4 r = *reinterpret_cast<const int4*>(rank + e);
        edst[__ldg(rowstart + s.x) + r.x] = d.x;
        edst[__ldg(rowstart + s.y) + r.y] = d.y;
        edst[__ldg(rowstart + s.z) + r.z] = d.z;
        edst[__ldg(rowstart + s.w) + r.w] = d.w;
    } else {
        for (int k = e; k < nedges; k++) {
            int s = __ldg(src + k);
            edst[__ldg(rowstart + s) + __ldg(rank + k)] = __ldg(dst + k);
        }
    }
}

// ---------------------------------------------------------------------------
// Kernel 6: aggregation (exact R10 structure — measured best, do not touch).
// ---------------------------------------------------------------------------
__global__ __launch_bounds__(256) void aggregate_kernel(
    const int* __restrict__ edst, const int* __restrict__ rowstart,
    const int* __restrict__ count,
    const float* __restrict__ ssrc, const float* __restrict__ sdst,
    const __half* __restrict__ Whh,
    float* __restrict__ out, int nrows)
{
    const int node = blockIdx.x * 32 + (threadIdx.x >> 3);
    const int t    = threadIdx.x & 7;
    const int lane = threadIdx.x & 31;
    const int base = lane & 24;
    const unsigned grpmask = 0xffu << base;
    if (node >= nrows) return;

    const int   start = __ldg(rowstart + node);
    const int   cnt   = __ldg(count + node);
    const float s0    = __ldg(ssrc + node);

    float a0 = 0.f, a1 = 0.f, a2 = 0.f, a3 = 0.f;
    float a4 = 0.f, a5 = 0.f, a6 = 0.f, a7 = 0.f;
    float wsum = 0.f;

    for (int j = 0; j < cnt; j += 8) {
        unsigned pk = 0;
        if (j + t < cnt) {
            int d = __ldg(edst + start + j + t);
            float score = s0 + __ldg(sdst + d);
            float l = score > 0.f ? score : ALPHA * score;
            float w = __expf(-l);
            pk = ((unsigned)d << 16) |
                 (unsigned)__half_as_ushort(__float2half_rn(w));
        }

        #pragma unroll
        for (int k = 0; k < 8; k++) {
            unsigned p  = __shfl_sync(grpmask, pk, base + k);
            int      dd = (int)(p >> 16);
            float    ww = __half2float(__ushort_as_half((unsigned short)(p & 0xffffu)));
            uint4 hv = __ldg(reinterpret_cast<const uint4*>(Whh + (size_t)dd * F_OUT) + t);
            float2 f0 = __half22float2(*reinterpret_cast<__half2*>(&hv.x));
            float2 f1 = __half22float2(*reinterpret_cast<__half2*>(&hv.y));
            float2 f2 = __half22float2(*reinterpret_cast<__half2*>(&hv.z));
            float2 f3 = __half22float2(*reinterpret_cast<__half2*>(&hv.w));
            a0 += ww * f0.x; a1 += ww * f0.y;
            a2 += ww * f1.x; a3 += ww * f1.y;
            a4 += ww * f2.x; a5 += ww * f2.y;
            a6 += ww * f3.x; a7 += ww * f3.y;
            wsum += ww;
        }
    }

    const float inv = 1.0f / wsum;
    a0 *= inv; a1 *= inv; a2 *= inv; a3 *= inv;
    a4 *= inv; a5 *= inv; a6 *= inv; a7 *= inv;
    a0 = a0 > 0.f ? a0 : expm1f(a0);
    a1 = a1 > 0.f ? a1 : expm1f(a1);
    a2 = a2 > 0.f ? a2 : expm1f(a2);
    a3 = a3 > 0.f ? a3 : expm1f(a3);
    a4 = a4 > 0.f ? a4 : expm1f(a4);
    a5 = a5 > 0.f ? a5 : expm1f(a5);
    a6 = a6 > 0.f ? a6 : expm1f(a6);
    a7 = a7 > 0.f ? a7 : expm1f(a7);

    float4* op = reinterpret_cast<float4*>(out + (size_t)node * F_OUT + t * 8);
    op[0] = make_float4(a0, a1, a2, a3);
    op[1] = make_float4(a4, a5, a6, a7);
}

// ---------------------------------------------------------------------------
// Launch — two independent chains captured as parallel graph branches.
// ---------------------------------------------------------------------------
extern "C" void kernel_launch(void* const* d_in, const int* in_sizes, int n_in,
                              void* d_out, int out_size)
{
    const float* x    = (const float*)d_in[0];
    const int*   edge = (const int*)d_in[1];
    const float* W    = (const float*)d_in[2];
    const float* a    = (const float*)d_in[3];
    float*       out  = (float*)d_out;

    const int nrows  = in_sizes[0] / F_IN;     // 50000
    const int nedges = in_sizes[1] / 2;        // 1600000
    const int* src = edge;
    const int* dst = edge + nedges;

    float *ssrc, *sdst;
    __half *Whh, *Wth, *Wtl;
    int *count, *rowstart, *blocksum, *rank, *edst;
    cudaGetSymbolAddress((void**)&Whh,      g_Whh);
    cudaGetSymbolAddress((void**)&Wth,      g_Wt_hi);
    cudaGetSymbolAddress((void**)&Wtl,      g_Wt_lo);
    cudaGetSymbolAddress((void**)&ssrc,     g_ssrc);
    cudaGetSymbolAddress((void**)&sdst,     g_sdst);
    cudaGetSymbolAddress((void**)&count,    g_count);
    cudaGetSymbolAddress((void**)&rowstart, g_rowstart);
    cudaGetSymbolAddress((void**)&blocksum, g_blocksum);
    cudaGetSymbolAddress((void**)&rank,     g_rank);
    cudaGetSymbolAddress((void**)&edst,     g_edst);

    const int nb = (nrows + SCAN_BLK - 1) / SCAN_BLK;   // 196 <= 256
    const int qthreads = (nedges + 3) / 4;

    static cudaStream_t s2 = nullptr;
    static cudaEvent_t  ev_fork = nullptr, ev_join = nullptr;
    if (s2 == nullptr) {
        cudaStreamCreateWithFlags(&s2, cudaStreamNonBlocking);
        cudaEventCreateWithFlags(&ev_fork, cudaEventDisableTiming);
        cudaEventCreateWithFlags(&ev_join, cudaEventDisableTiming);
    }

    // ---- fork
    cudaEventRecord(ev_fork, 0);
    cudaStreamWaitEvent(s2, ev_fork, 0);

    // ---- chain 1 (main stream): features + scores
    wprep_kernel<<<(F_IN * F_OUT + 255) / 256, 256>>>(W, Wth, Wtl);
    gemm_kernel<<<(nrows + BM - 1) / BM, 256>>>(x, Wth, Wtl, a, Whh, ssrc, sdst, nrows);

    // ---- chain 2 (s2): edge sorting (rank-based, single atomic pass)
    cudaMemsetAsync(count, 0, (size_t)nrows * sizeof(int), s2);
    hist_kernel<<<(qthreads + 255) / 256, 256, 0, s2>>>(src, count, rank, nedges);
    block_sum_kernel<<<nb, SCAN_BLK, 0, s2>>>(count, blocksum, nrows);
    scan_final_kernel<<<nb, SCAN_BLK, 0, s2>>>(count, blocksum, rowstart, nrows, nb);
    scatter_kernel<<<(qthreads + 255) / 256, 256, 0, s2>>>(src, dst, rowstart,
                                                           rank, edst, nedges);

    // ---- join
    cudaEventRecord(ev_join, s2);
    cudaStreamWaitEvent(0, ev_join, 0);

    // ---- aggregate + finalize
    aggregate_kernel<<<(nrows + 31) / 32, 256>>>(edst, rowstart, count,
                                                 ssrc, sdst, Whh, out, nrows);
}